// round 5
// baseline (speedup 1.0000x reference)
#include <cuda_runtime.h>
#include <cuda_bf16.h>
#include <math.h>

// Problem dims (fixed by the dataset)
#define NB 4
#define CH 3
#define HH 1080
#define WW 1920
#define HW (HH * WW)
#define NHW (NB * HW)

#define SZ_IN     (NB * 3 * HW)   // 24883200
#define SZ_FLOW   (NB * 2 * HW)   // 16588800
#define SZ_METRIC (NB * 1 * HW)   //  8294400

// Accumulator: [N, H, W, 4] interleaved (c0*m*w, c1*m*w, c2*m*w, m*w sums).
// Processed one batch image at a time so the active 33.2 MB slice stays
// L2-resident (126 MB L2) across zero -> splat -> norm.
__device__ float g_acc[(size_t)NHW * 4];

__global__ void zero_kernel(int b) {
    int i = blockIdx.x * blockDim.x + threadIdx.x;
    if (i < HW) {
        float4 z = make_float4(0.f, 0.f, 0.f, 0.f);
        reinterpret_cast<float4*>(g_acc)[(size_t)b * HW + i] = z;
    }
}

__global__ void splat_kernel(const float* __restrict__ in,
                             const float* __restrict__ flow,
                             const float* __restrict__ metric,
                             int b) {
    int rem = blockIdx.x * blockDim.x + threadIdx.x;
    if (rem >= HW) return;
    int y = rem / WW;
    int x = rem - y * WW;

    float fx = flow[(size_t)(b * 2 + 0) * HW + rem];
    float fy = flow[(size_t)(b * 2 + 1) * HW + rem];
    float tx = (float)x + fx;
    float ty = (float)y + fy;
    if (!isfinite(tx) || !isfinite(ty)) return;  // ref zeroes these contributions

    float m  = __expf(metric[(size_t)b * HW + rem]);
    float v0 = in[(size_t)(b * 3 + 0) * HW + rem] * m;
    float v1 = in[(size_t)(b * 3 + 1) * HW + rem] * m;
    float v2 = in[(size_t)(b * 3 + 2) * HW + rem] * m;

    float fxf = floorf(tx);
    float fyf = floorf(ty);
    int x0 = (int)fxf;
    int y0 = (int)fyf;
    float ax = tx - fxf;   // frac in [0,1)
    float ay = ty - fyf;

    float wx[2] = {1.f - ax, ax};
    float wy[2] = {1.f - ay, ay};

    float* base = g_acc + (size_t)b * HW * 4;

#pragma unroll
    for (int dy = 0; dy < 2; dy++) {
        int iy = y0 + dy;
        if (iy < 0 || iy >= HH) continue;
#pragma unroll
        for (int dx = 0; dx < 2; dx++) {
            int ix = x0 + dx;
            if (ix < 0 || ix >= WW) continue;
            float w = wx[dx] * wy[dy];
            float* ptr = base + ((size_t)iy * WW + ix) * 4;
            // One 16B vector reduction per corner; 4th lane accumulates m*w
            // (the reference's splatted exp(metric) channel).
            asm volatile(
                "red.global.add.v4.f32 [%0], {%1, %2, %3, %4};"
                :: "l"(ptr), "f"(v0 * w), "f"(v1 * w), "f"(v2 * w), "f"(m * w)
                : "memory");
        }
    }
}

__global__ void norm_kernel(float* __restrict__ out, int b) {
    int rem = blockIdx.x * blockDim.x + threadIdx.x;
    if (rem >= HW) return;
    float4 a = reinterpret_cast<const float4*>(g_acc)[(size_t)b * HW + rem];
    float inv = 1.0f / (a.w + 1e-7f);
    out[(size_t)(b * 3 + 0) * HW + rem] = a.x * inv;
    out[(size_t)(b * 3 + 1) * HW + rem] = a.y * inv;
    out[(size_t)(b * 3 + 2) * HW + rem] = a.z * inv;
}

extern "C" void kernel_launch(void* const* d_in, const int* in_sizes, int n_in,
                              void* d_out, int out_size) {
    // Identify inputs by element count — robust to any metadata ordering.
    const float* tenIn     = nullptr;
    const float* tenFlow   = nullptr;
    const float* tenMetric = nullptr;
    for (int i = 0; i < n_in; i++) {
        if      (in_sizes[i] == SZ_IN)     tenIn     = (const float*)d_in[i];
        else if (in_sizes[i] == SZ_FLOW)   tenFlow   = (const float*)d_in[i];
        else if (in_sizes[i] == SZ_METRIC) tenMetric = (const float*)d_in[i];
    }
    float* out = (float*)d_out;

    const int threads = 256;
    const int blocks  = (HW + threads - 1) / threads;  // 8100 per image

    // Per-batch pipeline: the 33.2 MB accumulator slice stays L2-resident
    // across its zero -> splat -> norm window, eliminating ~400 MB of
    // accumulator DRAM round-trips vs. full-frame passes.
    for (int b = 0; b < NB; b++) {
        zero_kernel <<<blocks, threads>>>(b);
        splat_kernel<<<blocks, threads>>>(tenIn, tenFlow, tenMetric, b);
        norm_kernel <<<blocks, threads>>>(out, b);
    }
}